// round 3
// baseline (speedup 1.0000x reference)
#include <cuda_runtime.h>

#define N_NODES   1000000
#define N_EDGES   16000000
#define NUM_GRAPHS 64
#define LATENT    128

// Global accumulators (scratch via __device__ globals per harness rules)
__device__ double g_recon;
__device__ double g_sumd2;
__device__ double g_sumlen;
__device__ float  g_gsum[2 * NUM_GRAPHS];
__device__ float  g_gcnt[NUM_GRAPHS];

__global__ void zero_kernel() {
    int t = threadIdx.x;
    if (t == 0) { g_recon = 0.0; g_sumd2 = 0.0; g_sumlen = 0.0; }
    if (t < NUM_GRAPHS) {
        g_gcnt[t] = 0.f;
        g_gsum[2 * t] = 0.f;
        g_gsum[2 * t + 1] = 0.f;
    }
}

// ---------------------------------------------------------------------------
// Node pass: recon MSE partial sum + per-graph position sums (drift)
// Each thread handles 2 nodes via float4 / int2 loads.
// ---------------------------------------------------------------------------
__global__ void node_kernel(const float4* __restrict__ pred,
                            const float4* __restrict__ tgt,
                            const int2*  __restrict__ batch,
                            int npairs) {
    __shared__ float sgs[2 * NUM_GRAPHS];
    __shared__ float sgc[NUM_GRAPHS];
    __shared__ float sred[8];

    int t = threadIdx.x;
    if (t < NUM_GRAPHS) {
        sgc[t] = 0.f;
        sgs[2 * t] = 0.f;
        sgs[2 * t + 1] = 0.f;
    }
    __syncthreads();

    int idx = blockIdx.x * blockDim.x + threadIdx.x;
    float rec = 0.f;
    if (idx < npairs) {
        float4 p = pred[idx];
        float4 q = tgt[idx];
        int2   b = batch[idx];
        float dx0 = p.x - q.x, dy0 = p.y - q.y;
        float dx1 = p.z - q.z, dy1 = p.w - q.w;
        rec = dx0 * dx0 + dy0 * dy0 + dx1 * dx1 + dy1 * dy1;
        atomicAdd(&sgs[2 * b.x],     p.x);
        atomicAdd(&sgs[2 * b.x + 1], p.y);
        atomicAdd(&sgc[b.x], 1.f);
        atomicAdd(&sgs[2 * b.y],     p.z);
        atomicAdd(&sgs[2 * b.y + 1], p.w);
        atomicAdd(&sgc[b.y], 1.f);
    }

    // block reduce rec
    #pragma unroll
    for (int o = 16; o > 0; o >>= 1)
        rec += __shfl_down_sync(0xffffffffu, rec, o);
    int w = threadIdx.x >> 5, l = threadIdx.x & 31;
    if (l == 0) sred[w] = rec;
    __syncthreads();
    if (threadIdx.x == 0) {
        float s = 0.f;
        #pragma unroll
        for (int i = 0; i < 8; i++) s += sred[i];
        atomicAdd(&g_recon, (double)s);
    }

    // flush per-graph sums (batch sorted -> most blocks touch <= 2 graphs)
    if (t < NUM_GRAPHS && sgc[t] != 0.f) {
        atomicAdd(&g_gcnt[t], sgc[t]);
        atomicAdd(&g_gsum[2 * t], sgs[2 * t]);
        atomicAdd(&g_gsum[2 * t + 1], sgs[2 * t + 1]);
    }
}

// ---------------------------------------------------------------------------
// Edge pass: gather pred[i], pred[j]; accumulate sum(d2) and sum(len).
// Each thread handles 4 edges via int4 loads of both index rows.
// ---------------------------------------------------------------------------
__global__ void edge_kernel(const int4* __restrict__ ei,
                            const int4* __restrict__ ej,
                            const float2* __restrict__ pred) {
    int t = blockIdx.x * blockDim.x + threadIdx.x;
    int4 a = ei[t];
    int4 b = ej[t];

    float s_d2 = 0.f, s_len = 0.f;

    {
        float2 pi = __ldg(&pred[a.x]); float2 pj = __ldg(&pred[b.x]);
        float dx = pi.x - pj.x, dy = pi.y - pj.y;
        float d2 = dx * dx + dy * dy;
        s_d2 += d2; s_len += sqrtf(d2);
    }
    {
        float2 pi = __ldg(&pred[a.y]); float2 pj = __ldg(&pred[b.y]);
        float dx = pi.x - pj.x, dy = pi.y - pj.y;
        float d2 = dx * dx + dy * dy;
        s_d2 += d2; s_len += sqrtf(d2);
    }
    {
        float2 pi = __ldg(&pred[a.z]); float2 pj = __ldg(&pred[b.z]);
        float dx = pi.x - pj.x, dy = pi.y - pj.y;
        float d2 = dx * dx + dy * dy;
        s_d2 += d2; s_len += sqrtf(d2);
    }
    {
        float2 pi = __ldg(&pred[a.w]); float2 pj = __ldg(&pred[b.w]);
        float dx = pi.x - pj.x, dy = pi.y - pj.y;
        float d2 = dx * dx + dy * dy;
        s_d2 += d2; s_len += sqrtf(d2);
    }

    #pragma unroll
    for (int o = 16; o > 0; o >>= 1) {
        s_d2  += __shfl_down_sync(0xffffffffu, s_d2, o);
        s_len += __shfl_down_sync(0xffffffffu, s_len, o);
    }
    __shared__ float smd2[8], smln[8];
    int w = threadIdx.x >> 5, l = threadIdx.x & 31;
    if (l == 0) { smd2[w] = s_d2; smln[w] = s_len; }
    __syncthreads();
    if (threadIdx.x == 0) {
        float d2 = 0.f, ln = 0.f;
        #pragma unroll
        for (int i = 0; i < 8; i++) { d2 += smd2[i]; ln += smln[i]; }
        atomicAdd(&g_sumd2, (double)d2);
        atomicAdd(&g_sumlen, (double)ln);
    }
}

// ---------------------------------------------------------------------------
// Finalize: KL over 64x128, drift from per-graph sums, compose total.
// ---------------------------------------------------------------------------
__global__ void final_kernel(const float* __restrict__ mu,
                             const float* __restrict__ logvar,
                             const int*  __restrict__ epoch,
                             float* __restrict__ out) {
    __shared__ float red[256];
    float kl = 0.f;
    for (int i = threadIdx.x; i < NUM_GRAPHS * LATENT; i += blockDim.x) {
        float m = mu[i], lv = logvar[i];
        kl += 1.f + lv - m * m - expf(lv);
    }
    red[threadIdx.x] = kl;
    __syncthreads();
    #pragma unroll
    for (int s = 128; s > 0; s >>= 1) {
        if (threadIdx.x < s) red[threadIdx.x] += red[threadIdx.x + s];
        __syncthreads();
    }
    if (threadIdx.x == 0) {
        double klv = -0.5 * (double)red[0] / (double)NUM_GRAPHS;

        double drift = 0.0;
        for (int g = 0; g < NUM_GRAPHS; g++) {
            double c  = (double)g_gcnt[g];
            double mx = (double)g_gsum[2 * g] / c;
            double my = (double)g_gsum[2 * g + 1] / c;
            drift += mx * mx + my * my;
        }
        drift /= (double)NUM_GRAPHS;

        double recon = g_recon / (2.0 * (double)N_NODES);
        double lap   = g_sumd2 / (double)N_EDGES;
        double meanlen = g_sumlen / (double)N_EDGES;
        double arap  = (g_sumd2 - (double)N_EDGES * meanlen * meanlen)
                       / ((double)N_EDGES - 1.0);

        int ep = *epoch;
        double beta = (ep < 10) ? (double)ep / 10.0 : 1.0;

        out[0] = (float)(recon + 0.1 * lap + 0.01 * drift
                         + 0.1 * arap + beta * klv);
    }
}

extern "C" void kernel_launch(void* const* d_in, const int* in_sizes, int n_in,
                              void* d_out, int out_size) {
    const float* pred   = (const float*)d_in[0];
    const float* target = (const float*)d_in[1];
    const int*   edges  = (const int*)d_in[2];
    const int*   batch  = (const int*)d_in[3];
    const float* mu     = (const float*)d_in[4];
    const float* logvar = (const float*)d_in[5];
    const int*   epoch  = (const int*)d_in[6];
    float* out = (float*)d_out;

    zero_kernel<<<1, 64>>>();

    int npairs = N_NODES / 2;  // 500,000
    int nblocks = (npairs + 255) / 256;
    node_kernel<<<nblocks, 256>>>((const float4*)pred, (const float4*)target,
                                  (const int2*)batch, npairs);

    // 16M edges, 4 per thread, 256 threads -> 15625 blocks (exact)
    edge_kernel<<<N_EDGES / (256 * 4), 256>>>(
        (const int4*)edges,
        (const int4*)(edges + N_EDGES),
        (const float2*)pred);

    final_kernel<<<1, 256>>>(mu, logvar, epoch, out);
}

// round 4
// speedup vs baseline: 1.1975x; 1.1975x over previous
#include <cuda_runtime.h>

#define N_NODES    1000000
#define N_EDGES    16000000
#define NUM_GRAPHS 64
#define LATENT     128

// Global accumulators (zero-initialized at module load; final_kernel re-zeros
// them at the end of every run so each graph replay starts clean).
__device__ double g_recon;
__device__ double g_sumd2;
__device__ double g_sumlen;
__device__ float  g_gsum[2 * NUM_GRAPHS];
__device__ float  g_gcnt[NUM_GRAPHS];

// ---------------------------------------------------------------------------
// Node pass: recon MSE partial sum + per-graph position sums (drift)
// Each thread handles 2 nodes via float4 / int2 loads.
// ---------------------------------------------------------------------------
__global__ void node_kernel(const float4* __restrict__ pred,
                            const float4* __restrict__ tgt,
                            const int2*  __restrict__ batch,
                            int npairs) {
    __shared__ float sgs[2 * NUM_GRAPHS];
    __shared__ float sgc[NUM_GRAPHS];
    __shared__ float sred[8];

    int t = threadIdx.x;
    if (t < NUM_GRAPHS) {
        sgc[t] = 0.f;
        sgs[2 * t] = 0.f;
        sgs[2 * t + 1] = 0.f;
    }
    __syncthreads();

    int idx = blockIdx.x * blockDim.x + threadIdx.x;
    float rec = 0.f;
    if (idx < npairs) {
        float4 p = pred[idx];
        float4 q = tgt[idx];
        int2   b = batch[idx];
        float dx0 = p.x - q.x, dy0 = p.y - q.y;
        float dx1 = p.z - q.z, dy1 = p.w - q.w;
        rec = dx0 * dx0 + dy0 * dy0 + dx1 * dx1 + dy1 * dy1;
        atomicAdd(&sgs[2 * b.x],     p.x);
        atomicAdd(&sgs[2 * b.x + 1], p.y);
        atomicAdd(&sgc[b.x], 1.f);
        atomicAdd(&sgs[2 * b.y],     p.z);
        atomicAdd(&sgs[2 * b.y + 1], p.w);
        atomicAdd(&sgc[b.y], 1.f);
    }

    // block reduce rec
    #pragma unroll
    for (int o = 16; o > 0; o >>= 1)
        rec += __shfl_down_sync(0xffffffffu, rec, o);
    int w = threadIdx.x >> 5, l = threadIdx.x & 31;
    if (l == 0) sred[w] = rec;
    __syncthreads();
    if (threadIdx.x == 0) {
        float s = 0.f;
        #pragma unroll
        for (int i = 0; i < 8; i++) s += sred[i];
        atomicAdd(&g_recon, (double)s);
    }

    // flush per-graph sums (batch sorted -> most blocks touch <= 2 graphs)
    if (t < NUM_GRAPHS && sgc[t] != 0.f) {
        atomicAdd(&g_gcnt[t], sgc[t]);
        atomicAdd(&g_gsum[2 * t], sgs[2 * t]);
        atomicAdd(&g_gsum[2 * t + 1], sgs[2 * t + 1]);
    }
}

// ---------------------------------------------------------------------------
// Edge pass: 8 edges per thread. 16 random float2 gathers front-batched for
// MLP; single-MUFU sqrt.approx per edge (d2=0 -> 0, safe for self-edges).
// ---------------------------------------------------------------------------
__global__ void __launch_bounds__(128)
edge_kernel(const int4* __restrict__ ei,
            const int4* __restrict__ ej,
            const float2* __restrict__ pred) {
    int t = blockIdx.x * blockDim.x + threadIdx.x;

    int4 a0 = ei[2 * t], a1 = ei[2 * t + 1];
    int4 b0 = ej[2 * t], b1 = ej[2 * t + 1];

    int ia[8] = {a0.x, a0.y, a0.z, a0.w, a1.x, a1.y, a1.z, a1.w};
    int ib[8] = {b0.x, b0.y, b0.z, b0.w, b1.x, b1.y, b1.z, b1.w};

    float2 pi[8], pj[8];
    #pragma unroll
    for (int k = 0; k < 8; k++) {
        pi[k] = __ldg(&pred[ia[k]]);
        pj[k] = __ldg(&pred[ib[k]]);
    }

    float s_d2 = 0.f, s_len = 0.f;
    #pragma unroll
    for (int k = 0; k < 8; k++) {
        float dx = pi[k].x - pj[k].x;
        float dy = pi[k].y - pj[k].y;
        float d2 = fmaf(dx, dx, dy * dy);
        float len;
        asm("sqrt.approx.f32 %0, %1;" : "=f"(len) : "f"(d2));
        s_d2  += d2;
        s_len += len;
    }

    #pragma unroll
    for (int o = 16; o > 0; o >>= 1) {
        s_d2  += __shfl_down_sync(0xffffffffu, s_d2, o);
        s_len += __shfl_down_sync(0xffffffffu, s_len, o);
    }
    __shared__ float smd2[4], smln[4];
    int w = threadIdx.x >> 5, l = threadIdx.x & 31;
    if (l == 0) { smd2[w] = s_d2; smln[w] = s_len; }
    __syncthreads();
    if (threadIdx.x == 0) {
        float d2 = 0.f, ln = 0.f;
        #pragma unroll
        for (int i = 0; i < 4; i++) { d2 += smd2[i]; ln += smln[i]; }
        atomicAdd(&g_sumd2, (double)d2);
        atomicAdd(&g_sumlen, (double)ln);
    }
}

// ---------------------------------------------------------------------------
// Finalize: KL over 64x128, parallel drift (64 threads, parallel fp64 divs),
// compose total, then re-zero accumulators for the next graph replay.
// ---------------------------------------------------------------------------
__global__ void final_kernel(const float* __restrict__ mu,
                             const float* __restrict__ logvar,
                             const int*  __restrict__ epoch,
                             float* __restrict__ out) {
    __shared__ float red[256];
    __shared__ double dred[NUM_GRAPHS];

    int t = threadIdx.x;

    float kl = 0.f;
    for (int i = t; i < NUM_GRAPHS * LATENT; i += blockDim.x) {
        float m = mu[i], lv = logvar[i];
        kl += 1.f + lv - m * m - expf(lv);
    }
    red[t] = kl;

    // parallel drift: one graph per thread, divides run concurrently
    if (t < NUM_GRAPHS) {
        double c  = (double)g_gcnt[t];
        double mx = (double)g_gsum[2 * t] / c;
        double my = (double)g_gsum[2 * t + 1] / c;
        dred[t] = mx * mx + my * my;
    }
    __syncthreads();

    #pragma unroll
    for (int s = 128; s > 0; s >>= 1) {
        if (t < s) red[t] += red[t + s];
        __syncthreads();
    }

    if (t == 0) {
        double klv = -0.5 * (double)red[0] / (double)NUM_GRAPHS;

        double drift = 0.0;
        #pragma unroll
        for (int g = 0; g < NUM_GRAPHS; g++) drift += dred[g];
        drift /= (double)NUM_GRAPHS;

        double recon = g_recon / (2.0 * (double)N_NODES);
        double lap   = g_sumd2 / (double)N_EDGES;
        double meanlen = g_sumlen / (double)N_EDGES;
        double arap  = (g_sumd2 - (double)N_EDGES * meanlen * meanlen)
                       / ((double)N_EDGES - 1.0);

        int ep = *epoch;
        double beta = (ep < 10) ? (double)ep / 10.0 : 1.0;

        out[0] = (float)(recon + 0.1 * lap + 0.01 * drift
                         + 0.1 * arap + beta * klv);
    }
    __syncthreads();

    // reset accumulators so the next replay starts from zero
    if (t == 0) { g_recon = 0.0; g_sumd2 = 0.0; g_sumlen = 0.0; }
    if (t < NUM_GRAPHS) {
        g_gcnt[t] = 0.f;
        g_gsum[2 * t] = 0.f;
        g_gsum[2 * t + 1] = 0.f;
    }
}

extern "C" void kernel_launch(void* const* d_in, const int* in_sizes, int n_in,
                              void* d_out, int out_size) {
    const float* pred   = (const float*)d_in[0];
    const float* target = (const float*)d_in[1];
    const int*   edges  = (const int*)d_in[2];
    const int*   batch  = (const int*)d_in[3];
    const float* mu     = (const float*)d_in[4];
    const float* logvar = (const float*)d_in[5];
    const int*   epoch  = (const int*)d_in[6];
    float* out = (float*)d_out;

    int npairs = N_NODES / 2;  // 500,000
    int nblocks = (npairs + 255) / 256;
    node_kernel<<<nblocks, 256>>>((const float4*)pred, (const float4*)target,
                                  (const int2*)batch, npairs);

    // 16M edges, 8 per thread, 128 threads -> 15625 blocks (exact)
    edge_kernel<<<N_EDGES / (128 * 8), 128>>>(
        (const int4*)edges,
        (const int4*)(edges + N_EDGES),
        (const float2*)pred);

    final_kernel<<<1, 256>>>(mu, logvar, epoch, out);
}

// round 5
// speedup vs baseline: 2.0271x; 1.6928x over previous
#include <cuda_runtime.h>

#define N_NODES    1000000
#define N_EDGES    16000000
#define NUM_GRAPHS 64
#define LATENT     128

// Global accumulators (zero-initialized at module load; final_kernel re-zeros
// them at the end of every run so each graph replay starts clean).
__device__ double g_recon;
__device__ double g_sumd2;
__device__ double g_sumlen;
__device__ float  g_gsum[2 * NUM_GRAPHS];
__device__ float  g_gcnt[NUM_GRAPHS];

// ---------------------------------------------------------------------------
// Node pass: recon MSE partial sum + per-graph position sums (drift).
// Each thread handles 2 nodes (float4/int2 loads). Grid is EXACT:
// 3125 blocks x 160 threads = 500,000 threads — every warp is full, so the
// warp-aggregation path can use full masks with no tail predication.
// batch_indices is sorted -> warp-uniform graph id in >99.9% of warps:
// shuffle-reduce within the warp and emit 3 shared atomics per warp instead
// of 192 (kills the ATOMS same-address serialization that cost 113us).
// ---------------------------------------------------------------------------
__global__ void __launch_bounds__(160)
node_kernel(const float4* __restrict__ pred,
            const float4* __restrict__ tgt,
            const int2*  __restrict__ batch) {
    __shared__ float sgs[2 * NUM_GRAPHS];
    __shared__ float sgc[NUM_GRAPHS];
    __shared__ float sred[5];

    int t = threadIdx.x;
    if (t < NUM_GRAPHS) {
        sgc[t] = 0.f;
        sgs[2 * t] = 0.f;
        sgs[2 * t + 1] = 0.f;
    }
    __syncthreads();

    int idx = blockIdx.x * blockDim.x + t;
    float4 p = pred[idx];
    float4 q = tgt[idx];
    int2   b = batch[idx];

    float dx0 = p.x - q.x, dy0 = p.y - q.y;
    float dx1 = p.z - q.z, dy1 = p.w - q.w;
    float rec = dx0 * dx0 + dy0 * dy0 + dx1 * dx1 + dy1 * dy1;

    const unsigned FULL = 0xffffffffu;
    int g0 = __shfl_sync(FULL, b.x, 0);
    bool uni = __all_sync(FULL, (b.x == g0) && (b.y == g0));
    int l = t & 31;

    if (uni) {
        // fast path: whole warp belongs to graph g0
        float sx = p.x + p.z;
        float sy = p.y + p.w;
        #pragma unroll
        for (int o = 16; o > 0; o >>= 1) {
            sx += __shfl_down_sync(FULL, sx, o);
            sy += __shfl_down_sync(FULL, sy, o);
        }
        if (l == 0) {
            atomicAdd(&sgs[2 * g0],     sx);
            atomicAdd(&sgs[2 * g0 + 1], sy);
            atomicAdd(&sgc[g0], 64.f);          // 32 lanes x 2 nodes
        }
    } else {
        // boundary warp (graph id changes inside warp) — rare
        atomicAdd(&sgs[2 * b.x],     p.x);
        atomicAdd(&sgs[2 * b.x + 1], p.y);
        atomicAdd(&sgc[b.x], 1.f);
        atomicAdd(&sgs[2 * b.y],     p.z);
        atomicAdd(&sgs[2 * b.y + 1], p.w);
        atomicAdd(&sgc[b.y], 1.f);
    }

    // block reduce rec (5 warps)
    #pragma unroll
    for (int o = 16; o > 0; o >>= 1)
        rec += __shfl_down_sync(FULL, rec, o);
    int w = t >> 5;
    if (l == 0) sred[w] = rec;
    __syncthreads();
    if (t == 0) {
        float s = 0.f;
        #pragma unroll
        for (int i = 0; i < 5; i++) s += sred[i];
        atomicAdd(&g_recon, (double)s);
    }

    // flush per-graph sums (sorted batch -> each block touches <= 2 graphs)
    if (t < NUM_GRAPHS && sgc[t] != 0.f) {
        atomicAdd(&g_gcnt[t], sgc[t]);
        atomicAdd(&g_gsum[2 * t], sgs[2 * t]);
        atomicAdd(&g_gsum[2 * t + 1], sgs[2 * t + 1]);
    }
}

// ---------------------------------------------------------------------------
// Edge pass: 8 edges per thread. 16 random float2 gathers front-batched for
// MLP; single-MUFU sqrt.approx per edge (d2=0 -> 0, safe for self-edges).
// L2-gather-bound: 32M x 32B sectors ~ 1GB of LTS traffic.
// ---------------------------------------------------------------------------
__global__ void __launch_bounds__(128)
edge_kernel(const int4* __restrict__ ei,
            const int4* __restrict__ ej,
            const float2* __restrict__ pred) {
    int t = blockIdx.x * blockDim.x + threadIdx.x;

    int4 a0 = ei[2 * t], a1 = ei[2 * t + 1];
    int4 b0 = ej[2 * t], b1 = ej[2 * t + 1];

    int ia[8] = {a0.x, a0.y, a0.z, a0.w, a1.x, a1.y, a1.z, a1.w};
    int ib[8] = {b0.x, b0.y, b0.z, b0.w, b1.x, b1.y, b1.z, b1.w};

    float2 pi[8], pj[8];
    #pragma unroll
    for (int k = 0; k < 8; k++) {
        pi[k] = __ldg(&pred[ia[k]]);
        pj[k] = __ldg(&pred[ib[k]]);
    }

    float s_d2 = 0.f, s_len = 0.f;
    #pragma unroll
    for (int k = 0; k < 8; k++) {
        float dx = pi[k].x - pj[k].x;
        float dy = pi[k].y - pj[k].y;
        float d2 = fmaf(dx, dx, dy * dy);
        float len;
        asm("sqrt.approx.f32 %0, %1;" : "=f"(len) : "f"(d2));
        s_d2  += d2;
        s_len += len;
    }

    #pragma unroll
    for (int o = 16; o > 0; o >>= 1) {
        s_d2  += __shfl_down_sync(0xffffffffu, s_d2, o);
        s_len += __shfl_down_sync(0xffffffffu, s_len, o);
    }
    __shared__ float smd2[4], smln[4];
    int w = threadIdx.x >> 5, l = threadIdx.x & 31;
    if (l == 0) { smd2[w] = s_d2; smln[w] = s_len; }
    __syncthreads();
    if (threadIdx.x == 0) {
        float d2 = 0.f, ln = 0.f;
        #pragma unroll
        for (int i = 0; i < 4; i++) { d2 += smd2[i]; ln += smln[i]; }
        atomicAdd(&g_sumd2, (double)d2);
        atomicAdd(&g_sumlen, (double)ln);
    }
}

// ---------------------------------------------------------------------------
// Finalize: KL over 64x128, parallel drift (64 threads, parallel fp64 divs),
// compose total, then re-zero accumulators for the next graph replay.
// ---------------------------------------------------------------------------
__global__ void final_kernel(const float* __restrict__ mu,
                             const float* __restrict__ logvar,
                             const int*  __restrict__ epoch,
                             float* __restrict__ out) {
    __shared__ float red[256];
    __shared__ double dred[NUM_GRAPHS];

    int t = threadIdx.x;

    float kl = 0.f;
    for (int i = t; i < NUM_GRAPHS * LATENT; i += blockDim.x) {
        float m = mu[i], lv = logvar[i];
        kl += 1.f + lv - m * m - expf(lv);
    }
    red[t] = kl;

    // parallel drift: one graph per thread, divides run concurrently
    if (t < NUM_GRAPHS) {
        double c  = (double)g_gcnt[t];
        double mx = (double)g_gsum[2 * t] / c;
        double my = (double)g_gsum[2 * t + 1] / c;
        dred[t] = mx * mx + my * my;
    }
    __syncthreads();

    #pragma unroll
    for (int s = 128; s > 0; s >>= 1) {
        if (t < s) red[t] += red[t + s];
        __syncthreads();
    }

    if (t == 0) {
        double klv = -0.5 * (double)red[0] / (double)NUM_GRAPHS;

        double drift = 0.0;
        #pragma unroll
        for (int g = 0; g < NUM_GRAPHS; g++) drift += dred[g];
        drift /= (double)NUM_GRAPHS;

        double recon = g_recon / (2.0 * (double)N_NODES);
        double lap   = g_sumd2 / (double)N_EDGES;
        double meanlen = g_sumlen / (double)N_EDGES;
        double arap  = (g_sumd2 - (double)N_EDGES * meanlen * meanlen)
                       / ((double)N_EDGES - 1.0);

        int ep = *epoch;
        double beta = (ep < 10) ? (double)ep / 10.0 : 1.0;

        out[0] = (float)(recon + 0.1 * lap + 0.01 * drift
                         + 0.1 * arap + beta * klv);
    }
    __syncthreads();

    // reset accumulators so the next replay starts from zero
    if (t == 0) { g_recon = 0.0; g_sumd2 = 0.0; g_sumlen = 0.0; }
    if (t < NUM_GRAPHS) {
        g_gcnt[t] = 0.f;
        g_gsum[2 * t] = 0.f;
        g_gsum[2 * t + 1] = 0.f;
    }
}

extern "C" void kernel_launch(void* const* d_in, const int* in_sizes, int n_in,
                              void* d_out, int out_size) {
    const float* pred   = (const float*)d_in[0];
    const float* target = (const float*)d_in[1];
    const int*   edges  = (const int*)d_in[2];
    const int*   batch  = (const int*)d_in[3];
    const float* mu     = (const float*)d_in[4];
    const float* logvar = (const float*)d_in[5];
    const int*   epoch  = (const int*)d_in[6];
    float* out = (float*)d_out;

    // 500,000 node-pairs = 3125 blocks x 160 threads (exact, full warps)
    node_kernel<<<3125, 160>>>((const float4*)pred, (const float4*)target,
                               (const int2*)batch);

    // 16M edges, 8 per thread, 128 threads -> 15625 blocks (exact)
    edge_kernel<<<N_EDGES / (128 * 8), 128>>>(
        (const int4*)edges,
        (const int4*)(edges + N_EDGES),
        (const float2*)pred);

    final_kernel<<<1, 256>>>(mu, logvar, epoch, out);
}

// round 6
// speedup vs baseline: 2.0836x; 1.0279x over previous
#include <cuda_runtime.h>

#define N_NODES    1000000
#define N_EDGES    16000000
#define NUM_GRAPHS 64
#define LATENT     128
#define NBLOCKS    15625     // 16M edges / (128 thr * 8 edges)

// Global accumulators (zero-initialized at module load; the final block
// re-zeros everything so each graph replay starts clean).
__device__ double   g_recon;
__device__ double   g_sumd2;
__device__ double   g_sumlen;
__device__ double   g_kl;
__device__ float    g_gsum[2 * NUM_GRAPHS];
__device__ float    g_gcnt[NUM_GRAPHS];
__device__ unsigned g_count;

// ---------------------------------------------------------------------------
// One fused kernel:
//   - every block: 1024 edges (8/thread, 16 front-batched L2 gathers/thread)
//   - warp 0 of every block: 32 node-pairs (recon MSE + drift segment sums,
//     warp-aggregated -> global atomics issued by tid 0 on the uniform path)
//   - block 0: KL over 64x128
//   - last block to finish (threadfence + counter): drift fp64 divides,
//     compose total, write out[0], reset all accumulators for replay
// The node/KL work executes under the LTS shadow of the edge gathers.
// ---------------------------------------------------------------------------
__global__ void __launch_bounds__(128)
fused_kernel(const float4* __restrict__ pred4,
             const float4* __restrict__ tgt4,
             const int2*  __restrict__ batch2,
             const int4*  __restrict__ ei,
             const int4*  __restrict__ ej,
             const float2* __restrict__ pred,
             const float* __restrict__ mu,
             const float* __restrict__ logvar,
             const int*  __restrict__ epoch,
             float* __restrict__ out) {
    const int tid = threadIdx.x;
    const int bid = blockIdx.x;
    const int l   = tid & 31;
    const int w   = tid >> 5;
    const unsigned FULL = 0xffffffffu;

    // ---- edge index loads first (long-latency DRAM, front-batched) ----
    const int t = bid * 128 + tid;
    int4 a0 = ei[2 * t], a1 = ei[2 * t + 1];
    int4 b0 = ej[2 * t], b1 = ej[2 * t + 1];

    // ---- node pass: warp 0 handles 32 float4-pairs (exact: 15625*32=500k) ----
    if (tid < 32) {
        int idx  = bid * 32 + tid;
        float4 p = pred4[idx];
        float4 q = tgt4[idx];
        int2   b = batch2[idx];

        float dx0 = p.x - q.x, dy0 = p.y - q.y;
        float dx1 = p.z - q.z, dy1 = p.w - q.w;
        float rec = dx0 * dx0 + dy0 * dy0 + dx1 * dx1 + dy1 * dy1;

        #pragma unroll
        for (int o = 16; o > 0; o >>= 1)
            rec += __shfl_down_sync(FULL, rec, o);

        int g0   = __shfl_sync(FULL, b.x, 0);
        bool uni = __all_sync(FULL, (b.x == g0) && (b.y == g0));

        if (uni) {
            float sx = p.x + p.z;
            float sy = p.y + p.w;
            #pragma unroll
            for (int o = 16; o > 0; o >>= 1) {
                sx += __shfl_down_sync(FULL, sx, o);
                sy += __shfl_down_sync(FULL, sy, o);
            }
            if (l == 0) {
                atomicAdd(&g_gsum[2 * g0],     sx);
                atomicAdd(&g_gsum[2 * g0 + 1], sy);
                atomicAdd(&g_gcnt[g0], 64.f);          // 32 lanes x 2 nodes
                atomicAdd(&g_recon, (double)rec);
            }
        } else {
            // boundary warp (graph id changes inside warp) — rare
            atomicAdd(&g_gsum[2 * b.x],     p.x);
            atomicAdd(&g_gsum[2 * b.x + 1], p.y);
            atomicAdd(&g_gcnt[b.x], 1.f);
            atomicAdd(&g_gsum[2 * b.y],     p.z);
            atomicAdd(&g_gsum[2 * b.y + 1], p.w);
            atomicAdd(&g_gcnt[b.y], 1.f);
            if (l == 0) atomicAdd(&g_recon, (double)rec);
            __threadfence();   // order these atomics before the done-counter
        }
    }

    // ---- KL: block 0 only (64x128 = 8192 elements over 128 threads) ----
    if (bid == 0) {
        __shared__ float kred[128];
        float kl = 0.f;
        for (int i = tid; i < NUM_GRAPHS * LATENT; i += 128) {
            float m = mu[i], lv = logvar[i];
            kl += 1.f + lv - m * m - expf(lv);
        }
        kred[tid] = kl;
        __syncthreads();
        #pragma unroll
        for (int s = 64; s > 0; s >>= 1) {
            if (tid < s) kred[tid] += kred[tid + s];
            __syncthreads();
        }
        if (tid == 0) g_kl = (double)kred[0];
    }

    // ---- edge pass: 8 edges/thread, 16 random gathers front-batched ----
    int ia[8] = {a0.x, a0.y, a0.z, a0.w, a1.x, a1.y, a1.z, a1.w};
    int ib[8] = {b0.x, b0.y, b0.z, b0.w, b1.x, b1.y, b1.z, b1.w};

    float2 pi[8], pj[8];
    #pragma unroll
    for (int k = 0; k < 8; k++) {
        pi[k] = __ldg(&pred[ia[k]]);
        pj[k] = __ldg(&pred[ib[k]]);
    }

    float s_d2 = 0.f, s_len = 0.f;
    #pragma unroll
    for (int k = 0; k < 8; k++) {
        float dx = pi[k].x - pj[k].x;
        float dy = pi[k].y - pj[k].y;
        float d2 = fmaf(dx, dx, dy * dy);
        float len;
        asm("sqrt.approx.f32 %0, %1;" : "=f"(len) : "f"(d2));
        s_d2  += d2;
        s_len += len;
    }

    #pragma unroll
    for (int o = 16; o > 0; o >>= 1) {
        s_d2  += __shfl_down_sync(FULL, s_d2, o);
        s_len += __shfl_down_sync(FULL, s_len, o);
    }
    __shared__ float smd2[4], smln[4];
    if (l == 0) { smd2[w] = s_d2; smln[w] = s_len; }
    __syncthreads();
    if (tid == 0) {
        float d2 = 0.f, ln = 0.f;
        #pragma unroll
        for (int i = 0; i < 4; i++) { d2 += smd2[i]; ln += smln[i]; }
        atomicAdd(&g_sumd2, (double)d2);
        atomicAdd(&g_sumlen, (double)ln);
    }

    // ---- completion protocol: last block finalizes ----
    __syncthreads();
    __shared__ bool s_last;
    if (tid == 0) {
        __threadfence();                 // release: my atomics before counter
        unsigned old = atomicAdd(&g_count, 1u);
        s_last = (old == NBLOCKS - 1);
    }
    __syncthreads();

    if (s_last) {
        __threadfence();                 // acquire: see all blocks' atomics
        __shared__ double dred[NUM_GRAPHS];
        if (tid < NUM_GRAPHS) {
            double c  = (double)__ldcg(&g_gcnt[tid]);
            double mx = (double)__ldcg(&g_gsum[2 * tid])     / c;
            double my = (double)__ldcg(&g_gsum[2 * tid + 1]) / c;
            dred[tid] = mx * mx + my * my;
        }
        __syncthreads();
        // reset per-graph accumulators for the next replay
        if (tid < NUM_GRAPHS) {
            g_gcnt[tid] = 0.f;
            g_gsum[2 * tid] = 0.f;
            g_gsum[2 * tid + 1] = 0.f;
        }
        if (tid == 0) {
            double drift = 0.0;
            #pragma unroll
            for (int g = 0; g < NUM_GRAPHS; g++) drift += dred[g];
            drift /= (double)NUM_GRAPHS;

            double sumd2  = __ldcg(&g_sumd2);
            double sumlen = __ldcg(&g_sumlen);
            double recon  = __ldcg(&g_recon) / (2.0 * (double)N_NODES);
            double klv    = -0.5 * __ldcg(&g_kl) / (double)NUM_GRAPHS;

            double lap     = sumd2 / (double)N_EDGES;
            double meanlen = sumlen / (double)N_EDGES;
            double arap    = (sumd2 - (double)N_EDGES * meanlen * meanlen)
                             / ((double)N_EDGES - 1.0);

            int ep = *epoch;
            double beta = (ep < 10) ? (double)ep / 10.0 : 1.0;

            out[0] = (float)(recon + 0.1 * lap + 0.01 * drift
                             + 0.1 * arap + beta * klv);

            // reset scalar accumulators + counter for the next replay
            g_recon = 0.0; g_sumd2 = 0.0; g_sumlen = 0.0; g_kl = 0.0;
            g_count = 0u;
        }
    }
}

extern "C" void kernel_launch(void* const* d_in, const int* in_sizes, int n_in,
                              void* d_out, int out_size) {
    const float* pred   = (const float*)d_in[0];
    const float* target = (const float*)d_in[1];
    const int*   edges  = (const int*)d_in[2];
    const int*   batch  = (const int*)d_in[3];
    const float* mu     = (const float*)d_in[4];
    const float* logvar = (const float*)d_in[5];
    const int*   epoch  = (const int*)d_in[6];
    float* out = (float*)d_out;

    fused_kernel<<<NBLOCKS, 128>>>(
        (const float4*)pred, (const float4*)target, (const int2*)batch,
        (const int4*)edges, (const int4*)(edges + N_EDGES),
        (const float2*)pred, mu, logvar, epoch, out);
}